// round 5
// baseline (speedup 1.0000x reference)
#include <cuda_runtime.h>

// ---------------- scratch (static device globals; no allocation) ----------------
__device__ float g_sig[64 * 4080];          // signature features, (64, 34*120) row-major
__device__ float g_hp[34 * 64 * 512];       // split-K partials of hidden layer

// ---------------- f32x2 packed helpers ----------------
__device__ __forceinline__ unsigned long long ffma2(unsigned long long a,
                                                    unsigned long long b,
                                                    unsigned long long c)
{
    unsigned long long d;
    asm("fma.rn.f32x2 %0, %1, %2, %3;" : "=l"(d) : "l"(a), "l"(b), "l"(c));
    return d;
}
__device__ __forceinline__ unsigned long long pack_dup(float x)
{
    unsigned long long d;
    asm("mov.b64 %0, {%1, %1};" : "=l"(d) : "f"(x));
    return d;
}

// ================= Kernel 1: depth-4 path signature =================
// 2176 paths (64 b x 34 vm). Block: 4 paths x 32 chunks = 128 threads, grid 544.
// Phase 0: cooperative smem staging of 4 paths (3600 floats, bulk MLP loads).
// Phase 1: factored Chen scan (183 FMA/step) reading staged smem (LDS).
// Phase 2: distributed tree combine, 1 barrier/level, c4 in place, L1-3 ping-pong.

__global__ void __launch_bounds__(128, 3) sig_kernel(const float* __restrict__ inp)
{
    extern __shared__ float sh[];
    float* P = sh;                       // 128 slots x 121 (also staging area [0,3600))
    float* Q = sh + 128 * 121;           // 64 slots x 41

    const int tid = threadIdx.x;
    const int pl = tid & 3;              // path within block (fixed per thread)
    const int chunk = tid >> 2;          // 0..31
    const int pbase = blockIdx.x * 4;
    const int p = pbase + pl;
    const int b = p / 34;
    const int vm = p - b * 34;
    const float* base = inp + b * 30600 + vm;   // + c*10200 + t*34

    // ---- phase 0: stage 4 paths x 3 ch x 300 t -> sh[(c*300+t)*4 + pl] ----
    {
        const int ct0 = tid >> 2;
#pragma unroll
        for (int it = 0; it < 29; it++) {
            const int ct = ct0 + it * 32;            // c*300 + t
            if (ct < 900) {
                const int c = (ct >= 300) + (ct >= 600);
                const int t = ct - c * 300;
                sh[ct * 4 + pl] = __ldg(base + c * 10200 + t * 34);
            }
        }
    }
    __syncthreads();

    const int s0 = (chunk * 299) >> 5;
    const int s1 = ((chunk + 1) * 299) >> 5;

    float c1[3], c2[9], c3[27], c4[81];
#pragma unroll
    for (int i = 0; i < 3; i++) c1[i] = 0.f;
#pragma unroll
    for (int i = 0; i < 9; i++) c2[i] = 0.f;
#pragma unroll
    for (int i = 0; i < 27; i++) c3[i] = 0.f;
#pragma unroll
    for (int i = 0; i < 81; i++) c4[i] = 0.f;

    // ---- phase 1: scan over staged data ----
    {
        const float* st = sh + s0 * 4 + pl;          // + (s-s0)*4 + c*1200
        float xp[3];
#pragma unroll
        for (int c = 0; c < 3; c++) xp[c] = st[c * 1200];

        for (int s = s0; s < s1; ++s) {
            const int o = (s - s0 + 1) * 4;
            float dx[3], dxh[3], dx3[3], e[3], bq[3], a[3];
#pragma unroll
            for (int i = 0; i < 3; i++) {
                const float xc = st[o + i * 1200];
                dx[i]  = xc - xp[i];
                xp[i]  = xc;
                dxh[i] = 0.5f * dx[i];
                dx3[i] = (1.0f / 3.0f) * dx[i];
                e[i]  = fmaf(0.25f, dx[i], c1[i]);
                bq[i] = c1[i] + dx3[i];
                a[i]  = c1[i] + dxh[i];
            }
            float q[9], sx[9];
#pragma unroll
            for (int i = 0; i < 3; i++)
#pragma unroll
                for (int j = 0; j < 3; j++) {
                    q[i * 3 + j]  = fmaf(e[i],  dx3[j], c2[i * 3 + j]);
                    sx[i * 3 + j] = fmaf(bq[i], dxh[j], c2[i * 3 + j]);
                }
#pragma unroll
            for (int i = 0; i < 3; i++)
#pragma unroll
                for (int j = 0; j < 3; j++)
#pragma unroll
                    for (int k = 0; k < 3; k++) {
                        const float r = fmaf(q[i * 3 + j], dxh[k], c3[i * 9 + j * 3 + k]);
                        const int x0 = i * 27 + j * 9 + k * 3;
#pragma unroll
                        for (int l = 0; l < 3; l++)
                            c4[x0 + l] = fmaf(r, dx[l], c4[x0 + l]);
                    }
#pragma unroll
            for (int i = 0; i < 3; i++)
#pragma unroll
                for (int j = 0; j < 3; j++)
#pragma unroll
                    for (int k = 0; k < 3; k++) {
                        const int x = i * 9 + j * 3 + k;
                        c3[x] = fmaf(sx[i * 3 + j], dx[k], c3[x]);
                    }
#pragma unroll
            for (int i = 0; i < 3; i++)
#pragma unroll
                for (int j = 0; j < 3; j++)
                    c2[i * 3 + j] = fmaf(a[i], dx[j], c2[i * 3 + j]);
#pragma unroll
            for (int i = 0; i < 3; i++) c1[i] += dx[i];
        }
    }

    // ---- all scans done before park overwrites the staging area ----
    __syncthreads();
    {
        float* w = P + tid * 121;
#pragma unroll
        for (int i = 0; i < 3; i++) w[i] = c1[i];
#pragma unroll
        for (int i = 0; i < 9; i++) w[3 + i] = c2[i];
#pragma unroll
        for (int i = 0; i < 27; i++) w[12 + i] = c3[i];
#pragma unroll
        for (int i = 0; i < 81; i++) w[39 + i] = c4[i];
    }
    __syncthreads();

    // ---- phase 2: 5-level distributed tree combine, 1 barrier/level ----
    int idx = 0;
#pragma unroll
    for (int d = 0; d < 5; d++) {
        idx = (idx << 1) | ((chunk >> d) & 1);
        const int aseg = (chunk >> (d + 1)) << 1;     // units of 2^d chunks
        const float* A13;
        const float* B13;
        float* dst;
        if ((d & 1) == 0) {                           // src P, dst Q
            A13 = P + ((aseg << d) * 4 + pl) * 121;
            B13 = P + (((aseg + 1) << d) * 4 + pl) * 121;
            dst = Q + ((aseg >> 1) * 4 + pl) * 41;
        } else {                                      // src Q, dst P
            A13 = Q + (aseg * 4 + pl) * 41;
            B13 = Q + ((aseg + 1) * 4 + pl) * 41;
            dst = P + (((aseg >> 1) << (d + 1)) * 4 + pl) * 121;
        }
        float* C4A = P + ((aseg << d) * 4 + pl) * 121 + 39;
        const float* C4B = P + (((aseg + 1) << d) * 4 + pl) * 121 + 39;

        const int gsh = d + 1;
        const int lo1 = (39 * idx) >> gsh, hi1 = (39 * (idx + 1)) >> gsh;
        const int lo4 = (81 * idx) >> gsh, hi4 = (81 * (idx + 1)) >> gsh;

        for (int e = lo1; e < hi1; e++) {             // L1-3 of merged segment
            float v = A13[e] + B13[e];
            if (e >= 12) {
                const int x = e - 12;
                const int ij = (x * 86) >> 8, k = x - 3 * ij;
                const int i2 = (x * 57) >> 9, jk = x - 9 * i2;
                v = fmaf(A13[3 + ij], B13[k], fmaf(A13[i2], B13[3 + jk], v));
            } else if (e >= 3) {
                const int x = e - 3;
                const int i2 = (x * 86) >> 8, j = x - 3 * i2;
                v = fmaf(A13[i2], B13[j], v);
            }
            dst[e] = v;
        }
        for (int e = lo4; e < hi4; e++) {             // L4, in place into A slot
            const int q3 = (e * 86) >> 8, l = e - 3 * q3;
            const int q9 = (e * 57) >> 9, kl = e - 9 * q9;
            const int i2 = (e * 19) >> 9, jkl = e - 27 * i2;
            float r = C4A[e] + C4B[e];
            r = fmaf(A13[12 + q3], B13[l], r);
            r = fmaf(A13[3 + q9],  B13[3 + kl], r);
            r = fmaf(A13[i2],      B13[12 + jkl], r);
            C4A[e] = r;
        }
        __syncthreads();
    }

    // ---- final: L1-3 in Q slot pl, c4 in P slot pl; coalesced store ----
#pragma unroll
    for (int it = 0; it < 4; it++) {
        const int idx2 = tid + it * 128;
        if (idx2 < 480) {
            const int pp = (idx2 * 547) >> 16;        // idx2 / 120
            const int r = idx2 - pp * 120;
            const float v = (r < 39) ? Q[pp * 41 + r] : P[pp * 121 + r];
            g_sig[pbase * 120 + idx2] = v;
        }
    }
}

// ================= Kernel 2: h-partials = sig @ W1^T (split-K 34) =================

__global__ void __launch_bounds__(128) gemm1_kernel(const float* __restrict__ W1)
{
    __shared__ float As[8][68];
    __shared__ float Bs[8][36];

    const int jt = blockIdx.x;          // 0..15
    const int ks = blockIdx.y;          // 0..33
    const int tid = threadIdx.x;
    const int tx = tid & 7;
    const int ty = tid >> 3;
    const int k0 = ks * 120;
    const int j0 = jt * 32;

    const int lrow = tid >> 1;          // 0..63
    const int lk4 = (tid & 1) * 4;      // 0 or 4
    const float* Aptr = g_sig + lrow * 4080 + k0 + lk4;
    const float* Bptr = W1 + (j0 + (lrow & 31)) * 4080 + k0 + lk4;
    const bool bload = (tid < 64);

    unsigned long long accp[4][2];
#pragma unroll
    for (int r = 0; r < 4; r++) { accp[r][0] = 0ull; accp[r][1] = 0ull; }

    float4 av = *(const float4*)(Aptr);
    float4 bv = bload ? *(const float4*)(Bptr) : make_float4(0, 0, 0, 0);

    for (int kt = 0; kt < 120; kt += 8) {
        __syncthreads();
        As[lk4 + 0][lrow] = av.x; As[lk4 + 1][lrow] = av.y;
        As[lk4 + 2][lrow] = av.z; As[lk4 + 3][lrow] = av.w;
        if (bload) {
            Bs[lk4 + 0][lrow] = bv.x; Bs[lk4 + 1][lrow] = bv.y;
            Bs[lk4 + 2][lrow] = bv.z; Bs[lk4 + 3][lrow] = bv.w;
        }
        if (kt < 112) {
            av = *(const float4*)(Aptr + kt + 8);
            if (bload) bv = *(const float4*)(Bptr + kt + 8);
        }
        __syncthreads();
#pragma unroll
        for (int kk = 0; kk < 8; kk++) {
            const float4 a = *(const float4*)&As[kk][ty * 4];
            const ulonglong2 bp = *(const ulonglong2*)&Bs[kk][tx * 4];
            unsigned long long aa;
            aa = pack_dup(a.x);
            accp[0][0] = ffma2(aa, bp.x, accp[0][0]);
            accp[0][1] = ffma2(aa, bp.y, accp[0][1]);
            aa = pack_dup(a.y);
            accp[1][0] = ffma2(aa, bp.x, accp[1][0]);
            accp[1][1] = ffma2(aa, bp.y, accp[1][1]);
            aa = pack_dup(a.z);
            accp[2][0] = ffma2(aa, bp.x, accp[2][0]);
            accp[2][1] = ffma2(aa, bp.y, accp[2][1]);
            aa = pack_dup(a.w);
            accp[3][0] = ffma2(aa, bp.x, accp[3][0]);
            accp[3][1] = ffma2(aa, bp.y, accp[3][1]);
        }
    }

    float* outp = g_hp + ks * 32768 + j0;
#pragma unroll
    for (int r = 0; r < 4; r++) {
        const unsigned long long v0 = accp[r][0], v1 = accp[r][1];
        float4 v;
        v.x = __uint_as_float((unsigned)(v0 & 0xffffffffu));
        v.y = __uint_as_float((unsigned)(v0 >> 32));
        v.z = __uint_as_float((unsigned)(v1 & 0xffffffffu));
        v.w = __uint_as_float((unsigned)(v1 >> 32));
        *(float4*)(outp + (ty * 4 + r) * 512 + tx * 4) = v;
    }
}

// ====== Kernel 3: out = (sum_s hp_s + b1) @ W2^T + b2, grid (64 rows, 5 j-tiles) ======

__global__ void __launch_bounds__(256) gemm2_kernel(const float* __restrict__ b1,
                                                    const float* __restrict__ W2,
                                                    const float* __restrict__ b2,
                                                    float* __restrict__ out)
{
    __shared__ float hs[512];
    const int i = blockIdx.x;
    const int jt = blockIdx.y;
    const int tid = threadIdx.x;

    for (int k = tid; k < 512; k += 256) {
        float v0 = b1[k], v1 = 0.f;
        const float* hp = g_hp + i * 512 + k;
#pragma unroll
        for (int s = 0; s < 34; s += 2) {
            v0 += hp[s * 32768];
            v1 += hp[(s + 1) * 32768];
        }
        hs[k] = v0 + v1;
    }
    __syncthreads();

    const int jl = tid >> 3;
    const int ell = tid & 7;
    if (jl < 31) {
        const int j = jt * 31 + jl;
        const float4* w = (const float4*)(W2 + j * 512) + ell;
        float acc0 = 0.f, acc1 = 0.f;
#pragma unroll
        for (int it = 0; it < 16; it += 2) {
            const float4 w0 = w[it * 8];
            const float4 w1 = w[(it + 1) * 8];
            const float* h0 = &hs[(ell + it * 8) * 4];
            const float* h1 = &hs[(ell + (it + 1) * 8) * 4];
            acc0 = fmaf(h0[0], w0.x, acc0); acc0 = fmaf(h0[1], w0.y, acc0);
            acc0 = fmaf(h0[2], w0.z, acc0); acc0 = fmaf(h0[3], w0.w, acc0);
            acc1 = fmaf(h1[0], w1.x, acc1); acc1 = fmaf(h1[1], w1.y, acc1);
            acc1 = fmaf(h1[2], w1.z, acc1); acc1 = fmaf(h1[3], w1.w, acc1);
        }
        float acc = acc0 + acc1;
#pragma unroll
        for (int m = 1; m < 8; m <<= 1)
            acc += __shfl_xor_sync(0xffffffffu, acc, m);
        if (ell == 0) out[i * 155 + j] = acc + b2[j];
    }
}

// ================================ launch =================================

extern "C" void kernel_launch(void* const* d_in, const int* in_sizes, int n_in,
                              void* d_out, int out_size)
{
    const float* inp = (const float*)d_in[0];
    const float* W1  = (const float*)d_in[1];
    const float* b1  = (const float*)d_in[2];
    const float* W2  = (const float*)d_in[3];
    const float* b2  = (const float*)d_in[4];
    float* out = (float*)d_out;

    const int sig_smem = (128 * 121 + 64 * 41) * (int)sizeof(float);   // 72448 B
    static int smem_set = 0;
    if (!smem_set) {
        cudaFuncSetAttribute(sig_kernel,
                             cudaFuncAttributeMaxDynamicSharedMemorySize, sig_smem);
        smem_set = 1;
    }

    sig_kernel<<<544, 128, sig_smem>>>(inp);
    gemm1_kernel<<<dim3(16, 34), 128>>>(W1);
    gemm2_kernel<<<dim3(64, 5), 256>>>(b1, W2, b2, out);
}

// round 6
// speedup vs baseline: 1.5410x; 1.5410x over previous
#include <cuda_runtime.h>

// ---------------- scratch (static device globals; no allocation) ----------------
__device__ float g_sig[64 * 4080];          // signature features, (64, 34*120) row-major
__device__ float g_hp[34 * 64 * 512];       // split-K partials of hidden layer

// ---------------- f32x2 packed helpers ----------------
__device__ __forceinline__ unsigned long long ffma2(unsigned long long a,
                                                    unsigned long long b,
                                                    unsigned long long c)
{
    unsigned long long d;
    asm("fma.rn.f32x2 %0, %1, %2, %3;" : "=l"(d) : "l"(a), "l"(b), "l"(c));
    return d;
}
__device__ __forceinline__ unsigned long long pack_dup(float x)
{
    unsigned long long d;
    asm("mov.b64 %0, {%1, %1};" : "=l"(d) : "f"(x));
    return d;
}

// ================= Kernel 1: depth-4 path signature =================
// R1 structure (measured best): 8 paths x 16 chunks = 128 threads, grid 272.
// Scan: factored Chen step (183 FMA, down from 264), __ldg + 1-step prefetch.
// Combine: serial 4-level tree in smem (contiguous slot access).

__global__ void __launch_bounds__(128) sig_kernel(const float* __restrict__ inp)
{
    __shared__ float xch[64][121];  // odd row stride -> conflict-free exchange

    const int tid = threadIdx.x;
    const int pl = tid & 7;         // path within block (fast -> coalesced)
    const int chunk = tid >> 3;     // 0..15
    const int p = blockIdx.x * 8 + pl;
    const int b = p / 34;
    const int vm = p - b * 34;
    const float* base = inp + b * 30600 + vm;   // inp[b][c][t][vm]: + c*10200 + t*34

    const int s0 = (chunk * 299) >> 4;
    const int s1 = ((chunk + 1) * 299) >> 4;

    float c1[3], c2[9], c3[27], c4[81];
#pragma unroll
    for (int i = 0; i < 3; i++) c1[i] = 0.f;
#pragma unroll
    for (int i = 0; i < 9; i++) c2[i] = 0.f;
#pragma unroll
    for (int i = 0; i < 27; i++) c3[i] = 0.f;
#pragma unroll
    for (int i = 0; i < 81; i++) c4[i] = 0.f;

    float xp[3], xc[3];
#pragma unroll
    for (int c = 0; c < 3; c++) xp[c] = __ldg(base + c * 10200 + s0 * 34);
#pragma unroll
    for (int c = 0; c < 3; c++) xc[c] = __ldg(base + c * 10200 + (s0 + 1) * 34);

    for (int s = s0; s < s1; ++s) {
        int tn = s + 2; if (tn > 299) tn = 299;   // clamped prefetch
        float xn[3];
#pragma unroll
        for (int c = 0; c < 3; c++) xn[c] = __ldg(base + c * 10200 + tn * 34);

        float dx[3], dxh[3], dx3[3], e[3], bq[3], a[3];
#pragma unroll
        for (int i = 0; i < 3; i++) {
            dx[i]  = xc[i] - xp[i];
            dxh[i] = 0.5f * dx[i];
            dx3[i] = (1.0f / 3.0f) * dx[i];
            e[i]  = fmaf(0.25f, dx[i], c1[i]);   // c1 + dx/4
            bq[i] = c1[i] + dx3[i];              // c1 + dx/3
            a[i]  = c1[i] + dxh[i];              // c1 + dx/2
        }
        float q[9], sx[9];
#pragma unroll
        for (int i = 0; i < 3; i++)
#pragma unroll
            for (int j = 0; j < 3; j++) {
                q[i * 3 + j]  = fmaf(e[i],  dx3[j], c2[i * 3 + j]);
                sx[i * 3 + j] = fmaf(bq[i], dxh[j], c2[i * 3 + j]);
            }
        // level 4: c4 += (c3[ijk] + q[ij]*dxh[k]) * dx[l]   (108 FMA)
#pragma unroll
        for (int i = 0; i < 3; i++)
#pragma unroll
            for (int j = 0; j < 3; j++)
#pragma unroll
                for (int k = 0; k < 3; k++) {
                    const float r = fmaf(q[i * 3 + j], dxh[k], c3[i * 9 + j * 3 + k]);
                    const int x0 = i * 27 + j * 9 + k * 3;
#pragma unroll
                    for (int l = 0; l < 3; l++)
                        c4[x0 + l] = fmaf(r, dx[l], c4[x0 + l]);
                }
        // level 3: c3 += sx[ij] * dx[k]   (27 FMA)
#pragma unroll
        for (int i = 0; i < 3; i++)
#pragma unroll
            for (int j = 0; j < 3; j++)
#pragma unroll
                for (int k = 0; k < 3; k++) {
                    const int x = i * 9 + j * 3 + k;
                    c3[x] = fmaf(sx[i * 3 + j], dx[k], c3[x]);
                }
        // level 2
#pragma unroll
        for (int i = 0; i < 3; i++)
#pragma unroll
            for (int j = 0; j < 3; j++)
                c2[i * 3 + j] = fmaf(a[i], dx[j], c2[i * 3 + j]);
        // level 1
#pragma unroll
        for (int i = 0; i < 3; i++) c1[i] += dx[i];

#pragma unroll
        for (int c = 0; c < 3; c++) { xp[c] = xc[c]; xc[c] = xn[c]; }
    }

    // ---- tree combine across chunks (Chen: a = earlier (mine), b = later) ----
#pragma unroll
    for (int d = 0; d < 4; d++) {
        const int step = 1 << d;
        const int m2 = (step << 1) - 1;
        const int slot = pl + 8 * (chunk >> (d + 1));
        __syncthreads();
        if ((chunk & m2) == step) {           // writer: the "later" half
            float* w = xch[slot];
#pragma unroll
            for (int i = 0; i < 3; i++) w[i] = c1[i];
#pragma unroll
            for (int i = 0; i < 9; i++) w[3 + i] = c2[i];
#pragma unroll
            for (int i = 0; i < 27; i++) w[12 + i] = c3[i];
#pragma unroll
            for (int i = 0; i < 81; i++) w[39 + i] = c4[i];
        }
        __syncthreads();
        if ((chunk & m2) == 0) {              // reader/combiner: the "earlier" half
            const float* B = xch[slot];
            float bb1[3], bb2[9], bb3[27];
#pragma unroll
            for (int i = 0; i < 3; i++) bb1[i] = B[i];
#pragma unroll
            for (int i = 0; i < 9; i++) bb2[i] = B[3 + i];
#pragma unroll
            for (int i = 0; i < 27; i++) bb3[i] = B[12 + i];

#pragma unroll
            for (int i = 0; i < 3; i++)
#pragma unroll
                for (int j = 0; j < 3; j++)
#pragma unroll
                    for (int k = 0; k < 3; k++)
#pragma unroll
                        for (int l = 0; l < 3; l++) {
                            const int x = i * 27 + j * 9 + k * 3 + l;
                            c4[x] = fmaf(c3[i * 9 + j * 3 + k], bb1[l],
                                    fmaf(c2[i * 3 + j], bb2[k * 3 + l],
                                    fmaf(c1[i], bb3[j * 9 + k * 3 + l],
                                         c4[x] + B[39 + x])));
                        }
#pragma unroll
            for (int i = 0; i < 3; i++)
#pragma unroll
                for (int j = 0; j < 3; j++)
#pragma unroll
                    for (int k = 0; k < 3; k++) {
                        const int x = i * 9 + j * 3 + k;
                        c3[x] = fmaf(c2[i * 3 + j], bb1[k],
                                fmaf(c1[i], bb2[j * 3 + k], c3[x] + bb3[x]));
                    }
#pragma unroll
            for (int i = 0; i < 3; i++)
#pragma unroll
                for (int j = 0; j < 3; j++)
                    c2[i * 3 + j] = fmaf(c1[i], bb1[j], c2[i * 3 + j] + bb2[i * 3 + j]);
#pragma unroll
            for (int i = 0; i < 3; i++) c1[i] += bb1[i];
        }
    }

    if (chunk == 0) {
        float* out = g_sig + p * 120;
#pragma unroll
        for (int i = 0; i < 3; i++) out[i] = c1[i];
#pragma unroll
        for (int i = 0; i < 9; i++) out[3 + i] = c2[i];
#pragma unroll
        for (int i = 0; i < 27; i++) out[12 + i] = c3[i];
#pragma unroll
        for (int i = 0; i < 81; i++) out[39 + i] = c4[i];
    }
}

// ================= Kernel 2: h-partials = sig @ W1^T (split-K 34) =================

__global__ void __launch_bounds__(128) gemm1_kernel(const float* __restrict__ W1)
{
    __shared__ float As[8][68];
    __shared__ float Bs[8][36];

    const int jt = blockIdx.x;          // 0..15
    const int ks = blockIdx.y;          // 0..33
    const int tid = threadIdx.x;
    const int tx = tid & 7;
    const int ty = tid >> 3;
    const int k0 = ks * 120;
    const int j0 = jt * 32;

    const int lrow = tid >> 1;          // 0..63
    const int lk4 = (tid & 1) * 4;      // 0 or 4
    const float* Aptr = g_sig + lrow * 4080 + k0 + lk4;
    const float* Bptr = W1 + (j0 + (lrow & 31)) * 4080 + k0 + lk4;
    const bool bload = (tid < 64);

    unsigned long long accp[4][2];
#pragma unroll
    for (int r = 0; r < 4; r++) { accp[r][0] = 0ull; accp[r][1] = 0ull; }

    float4 av = *(const float4*)(Aptr);
    float4 bv = bload ? *(const float4*)(Bptr) : make_float4(0, 0, 0, 0);

    for (int kt = 0; kt < 120; kt += 8) {
        __syncthreads();
        As[lk4 + 0][lrow] = av.x; As[lk4 + 1][lrow] = av.y;
        As[lk4 + 2][lrow] = av.z; As[lk4 + 3][lrow] = av.w;
        if (bload) {
            Bs[lk4 + 0][lrow] = bv.x; Bs[lk4 + 1][lrow] = bv.y;
            Bs[lk4 + 2][lrow] = bv.z; Bs[lk4 + 3][lrow] = bv.w;
        }
        if (kt < 112) {
            av = *(const float4*)(Aptr + kt + 8);
            if (bload) bv = *(const float4*)(Bptr + kt + 8);
        }
        __syncthreads();
#pragma unroll
        for (int kk = 0; kk < 8; kk++) {
            const float4 a = *(const float4*)&As[kk][ty * 4];
            const ulonglong2 bp = *(const ulonglong2*)&Bs[kk][tx * 4];
            unsigned long long aa;
            aa = pack_dup(a.x);
            accp[0][0] = ffma2(aa, bp.x, accp[0][0]);
            accp[0][1] = ffma2(aa, bp.y, accp[0][1]);
            aa = pack_dup(a.y);
            accp[1][0] = ffma2(aa, bp.x, accp[1][0]);
            accp[1][1] = ffma2(aa, bp.y, accp[1][1]);
            aa = pack_dup(a.z);
            accp[2][0] = ffma2(aa, bp.x, accp[2][0]);
            accp[2][1] = ffma2(aa, bp.y, accp[2][1]);
            aa = pack_dup(a.w);
            accp[3][0] = ffma2(aa, bp.x, accp[3][0]);
            accp[3][1] = ffma2(aa, bp.y, accp[3][1]);
        }
    }

    float* outp = g_hp + ks * 32768 + j0;
#pragma unroll
    for (int r = 0; r < 4; r++) {
        const unsigned long long v0 = accp[r][0], v1 = accp[r][1];
        float4 v;
        v.x = __uint_as_float((unsigned)(v0 & 0xffffffffu));
        v.y = __uint_as_float((unsigned)(v0 >> 32));
        v.z = __uint_as_float((unsigned)(v1 & 0xffffffffu));
        v.w = __uint_as_float((unsigned)(v1 >> 32));
        *(float4*)(outp + (ty * 4 + r) * 512 + tx * 4) = v;
    }
}

// ====== Kernel 3: out = (sum_s hp_s + b1) @ W2^T + b2, grid (64 rows, 5 j-tiles) ======

__global__ void __launch_bounds__(256) gemm2_kernel(const float* __restrict__ b1,
                                                    const float* __restrict__ W2,
                                                    const float* __restrict__ b2,
                                                    float* __restrict__ out)
{
    __shared__ float hs[512];
    const int i = blockIdx.x;
    const int jt = blockIdx.y;
    const int tid = threadIdx.x;

    for (int k = tid; k < 512; k += 256) {
        float v0 = b1[k], v1 = 0.f;
        const float* hp = g_hp + i * 512 + k;
#pragma unroll
        for (int s = 0; s < 34; s += 2) {
            v0 += hp[s * 32768];
            v1 += hp[(s + 1) * 32768];
        }
        hs[k] = v0 + v1;
    }
    __syncthreads();

    const int jl = tid >> 3;
    const int ell = tid & 7;
    if (jl < 31) {
        const int j = jt * 31 + jl;
        const float4* w = (const float4*)(W2 + j * 512) + ell;
        float acc0 = 0.f, acc1 = 0.f;
#pragma unroll
        for (int it = 0; it < 16; it += 2) {
            const float4 w0 = w[it * 8];
            const float4 w1 = w[(it + 1) * 8];
            const float* h0 = &hs[(ell + it * 8) * 4];
            const float* h1 = &hs[(ell + (it + 1) * 8) * 4];
            acc0 = fmaf(h0[0], w0.x, acc0); acc0 = fmaf(h0[1], w0.y, acc0);
            acc0 = fmaf(h0[2], w0.z, acc0); acc0 = fmaf(h0[3], w0.w, acc0);
            acc1 = fmaf(h1[0], w1.x, acc1); acc1 = fmaf(h1[1], w1.y, acc1);
            acc1 = fmaf(h1[2], w1.z, acc1); acc1 = fmaf(h1[3], w1.w, acc1);
        }
        float acc = acc0 + acc1;
#pragma unroll
        for (int m = 1; m < 8; m <<= 1)
            acc += __shfl_xor_sync(0xffffffffu, acc, m);
        if (ell == 0) out[i * 155 + j] = acc + b2[j];
    }
}

// ================================ launch =================================

extern "C" void kernel_launch(void* const* d_in, const int* in_sizes, int n_in,
                              void* d_out, int out_size)
{
    const float* inp = (const float*)d_in[0];
    const float* W1  = (const float*)d_in[1];
    const float* b1  = (const float*)d_in[2];
    const float* W2  = (const float*)d_in[3];
    const float* b2  = (const float*)d_in[4];
    float* out = (float*)d_out;

    sig_kernel<<<272, 128>>>(inp);
    gemm1_kernel<<<dim3(16, 34), 128>>>(W1);
    gemm2_kernel<<<dim3(64, 5), 256>>>(b1, W2, b2, out);
}